// round 16
// baseline (speedup 1.0000x reference)
#include <cuda_runtime.h>
#include <math.h>
#include <stdint.h>

// Problem dims (fixed)
#define Bc 4
#define Lc 2048
#define Hc 8
#define Dc 64
#define Mc 256
#define CHK 64
#define NCH (Lc/CHK)         // 32
#define BH (Bc*Hc)           // 32
#define NROWS (Bc*Lc*Hc)     // 65536

#define NORMC 0.35355339059327373f   // 64^(-1/4)
#define RATIO 0.0625f                // 1/sqrt(256)
#define DIAGC 0.0625f                // 0.5 * 64^(-1/2)
#define KEPS  1e-4f
#define BETA  (RATIO*KEPS)

// ----- scratch (static device arrays; no allocation) -----
__device__ float g_qp [(size_t)BH*Lc*Mc];      // 64 MB [bh][l][m] query features
__device__ float g_E  [(size_t)BH*Lc*Mc];      // 64 MB exp(dash - diag) for keys
__device__ float g_S  [(size_t)BH*NCH*Mc*Dc];  // 64 MB EXCLUSIVE prefix states [m][d]
__device__ float g_z  [(size_t)BH*NCH*Mc];     // exclusive prefix z
__device__ float g_kmax[BH];

__device__ __forceinline__ void atomicMaxF(float* addr, float v){
    int old = __float_as_int(*addr);
    while (__int_as_float(old) < v){
        int assumed = old;
        old = atomicCAS((int*)addr, assumed, __float_as_int(v));
        if (old == assumed) break;
    }
}

// fp32 -> tf32 (round-to-nearest), kept in a float register slot
__device__ __forceinline__ float tf32f(float f){
    uint32_t r;
    asm("cvt.rna.tf32.f32 %0, %1;" : "=r"(r) : "f"(f));
    return __uint_as_float(r);
}

__device__ __forceinline__ void mma_tf32(float& d0, float& d1, float& d2, float& d3,
                                         uint32_t a0, uint32_t a1, uint32_t a2, uint32_t a3,
                                         uint32_t b0, uint32_t b1){
    asm volatile("mma.sync.aligned.m16n8k8.row.col.f32.tf32.tf32.f32 "
        "{%0,%1,%2,%3}, {%4,%5,%6,%7}, {%8,%9}, {%0,%1,%2,%3};"
        : "+f"(d0), "+f"(d1), "+f"(d2), "+f"(d3)
        : "r"(a0), "r"(a1), "r"(a2), "r"(a3), "r"(b0), "r"(b1));
}

__global__ void init_kernel(){
    if (threadIdx.x < BH) g_kmax[threadIdx.x] = -3.0e38f;
}

// ============================================================
// K1: features via mma.sync tf32x3 (R14 version, unchanged).
// ============================================================
#define OPF 68

__global__ __launch_bounds__(256,2) void feat_kernel(const float* __restrict__ X,
                                                     const float* __restrict__ P,
                                                     int isQuery)
{
    extern __shared__ float sm[];
    float* X1   = sm;                 // [64][OPF]
    float* X2   = X1 + 64*OPF;        // [64][OPF]
    float* P1   = X2 + 64*OPF;        // [64][OPF]
    float* P2   = P1 + 64*OPF;        // [64][OPF]
    float* ssd  = P2 + 64*OPF;        // [64]
    float* pmax = ssd + 64;           // [2][64]

    const int tid = threadIdx.x;
    const int w = tid >> 5, lane = tid & 31;
    const int lr = lane >> 2, lc = lane & 3;
    const int tg = w & 3, nh = w >> 2;
    const int row0 = blockIdx.x * 64;

    for (int i = tid; i < 1024; i += 256){
        int r = i >> 4, d4 = (i & 15)*4;
        float4 v = *(const float4*)&X[(size_t)(row0 + r)*Dc + d4];
        float4 xt = make_float4(v.x*NORMC, v.y*NORMC, v.z*NORMC, v.w*NORMC);
        float4 h = make_float4(tf32f(xt.x), tf32f(xt.y), tf32f(xt.z), tf32f(xt.w));
        float4 l = make_float4(tf32f(xt.x - h.x), tf32f(xt.y - h.y),
                               tf32f(xt.z - h.z), tf32f(xt.w - h.w));
        *(float4*)&X1[r*OPF + d4] = h;
        *(float4*)&X2[r*OPF + d4] = l;
    }
    __syncthreads();

    if (tid < 64){
        float s = 0.f;
        #pragma unroll
        for (int d = 0; d < 64; d++){
            float v = X1[tid*OPF + d] + X2[tid*OPF + d];
            s += v*v;
        }
        ssd[tid] = 0.5f * s;
    }

    const int t_lo = tg*16 + lr;
    const int t_hi = t_lo + 8;

    float acc[16][4];
    #pragma unroll
    for (int j = 0; j < 16; j++)
        #pragma unroll
        for (int r = 0; r < 4; r++) acc[j][r] = 0.f;

    for (int mt = 0; mt < 4; mt++){
        __syncthreads();
        for (int i = tid; i < 1024; i += 256){
            int mm = i >> 4, d4 = (i & 15)*4;
            float4 v = *(const float4*)&P[(size_t)(mt*64 + mm)*Dc + d4];
            float4 h = make_float4(tf32f(v.x), tf32f(v.y), tf32f(v.z), tf32f(v.w));
            float4 l = make_float4(tf32f(v.x - h.x), tf32f(v.y - h.y),
                                   tf32f(v.z - h.z), tf32f(v.w - h.w));
            *(float4*)&P1[mm*OPF + d4] = h;
            *(float4*)&P2[mm*OPF + d4] = l;
        }
        __syncthreads();

        #pragma unroll
        for (int ks = 0; ks < 8; ks++){
            const int k0 = ks*8;
            const float* a1p = &X1[t_lo*OPF + k0 + lc];
            const float* a2p = &X2[t_lo*OPF + k0 + lc];
            uint32_t a10 = __float_as_uint(a1p[0]);
            uint32_t a11 = __float_as_uint(a1p[8*OPF]);
            uint32_t a12 = __float_as_uint(a1p[4]);
            uint32_t a13 = __float_as_uint(a1p[8*OPF + 4]);
            uint32_t a20 = __float_as_uint(a2p[0]);
            uint32_t a21 = __float_as_uint(a2p[8*OPF]);
            uint32_t a22 = __float_as_uint(a2p[4]);
            uint32_t a23 = __float_as_uint(a2p[8*OPF + 4]);
            #pragma unroll
            for (int j = 0; j < 4; j++){
                const int nrow = nh*32 + j*8 + lr;
                uint32_t b10 = __float_as_uint(P1[nrow*OPF + k0 + lc]);
                uint32_t b11 = __float_as_uint(P1[nrow*OPF + k0 + 4 + lc]);
                uint32_t b20 = __float_as_uint(P2[nrow*OPF + k0 + lc]);
                uint32_t b21 = __float_as_uint(P2[nrow*OPF + k0 + 4 + lc]);
                const int jj = mt*4 + j;
                mma_tf32(acc[jj][0], acc[jj][1], acc[jj][2], acc[jj][3],
                         a10, a11, a12, a13, b10, b11);
                mma_tf32(acc[jj][0], acc[jj][1], acc[jj][2], acc[jj][3],
                         a20, a21, a22, a23, b10, b11);
                mma_tf32(acc[jj][0], acc[jj][1], acc[jj][2], acc[jj][3],
                         a10, a11, a12, a13, b20, b21);
            }
        }
    }

    float mxL = -3.0e38f, mxH = -3.0e38f;
    #pragma unroll
    for (int jj = 0; jj < 16; jj++){
        mxL = fmaxf(mxL, fmaxf(acc[jj][0], acc[jj][1]));
        mxH = fmaxf(mxH, fmaxf(acc[jj][2], acc[jj][3]));
    }
    mxL = fmaxf(mxL, __shfl_xor_sync(0xffffffffu, mxL, 1));
    mxL = fmaxf(mxL, __shfl_xor_sync(0xffffffffu, mxL, 2));
    mxH = fmaxf(mxH, __shfl_xor_sync(0xffffffffu, mxH, 1));
    mxH = fmaxf(mxH, __shfl_xor_sync(0xffffffffu, mxH, 2));
    __syncthreads();
    if (lc == 0){
        pmax[nh*64 + t_lo] = mxL;
        pmax[nh*64 + t_hi] = mxH;
    }
    __syncthreads();
    mxL = fmaxf(pmax[t_lo], pmax[64 + t_lo]);
    mxH = fmaxf(pmax[t_hi], pmax[64 + t_hi]);

    const int growL = row0 + t_lo;
    const int growH = row0 + t_hi;
    const int bhL = ((growL >> 3) >> 11)*Hc + (growL & 7);
    const int lL  = (growL >> 3) & 2047;
    const int bhH = ((growH >> 3) >> 11)*Hc + (growH & 7);
    const int lH  = (growH >> 3) & 2047;
    const float diagL = ssd[t_lo];
    const float diagH = ssd[t_hi];
    const size_t drowL = ((size_t)bhL*Lc + lL)*Mc;
    const size_t drowH = ((size_t)bhH*Lc + lH)*Mc;

    if (isQuery){
        #pragma unroll
        for (int jj = 0; jj < 16; jj++){
            const int col = (jj >> 2)*64 + nh*32 + (jj & 3)*8 + lc*2;
            float2 oL = make_float2(
                RATIO * (__expf(acc[jj][0] - diagL - mxL) + KEPS),
                RATIO * (__expf(acc[jj][1] - diagL - mxL) + KEPS));
            float2 oH = make_float2(
                RATIO * (__expf(acc[jj][2] - diagH - mxH) + KEPS),
                RATIO * (__expf(acc[jj][3] - diagH - mxH) + KEPS));
            *(float2*)&g_qp[drowL + col] = oL;
            *(float2*)&g_qp[drowH + col] = oH;
        }
    } else {
        #pragma unroll
        for (int jj = 0; jj < 16; jj++){
            const int col = (jj >> 2)*64 + nh*32 + (jj & 3)*8 + lc*2;
            float2 oL = make_float2(__expf(acc[jj][0] - diagL),
                                    __expf(acc[jj][1] - diagL));
            float2 oH = make_float2(__expf(acc[jj][2] - diagH),
                                    __expf(acc[jj][3] - diagH));
            *(float2*)&g_E[drowL + col] = oL;
            *(float2*)&g_E[drowH + col] = oH;
        }
        if (nh == 0 && lc == 0){
            atomicMaxF(&g_kmax[bhL], mxL);
            atomicMaxF(&g_kmax[bhH], mxH);
        }
    }
}

// ============================================================
// K3 v4 (scan): fused state + exclusive prefix.
// Block = (bh, 16-m slice); walks 32 chunks sequentially.
// Per chunk: stage kp-tile + V-tile, WRITE running prefix (exclusive),
// then mma-accumulate the chunk into running registers.
// Warp w owns (16 m) x (8 d = w*8..): running acc = 4 regs.
// ============================================================
#define KTP2 24        // [64 t][KTP2] kp tile (16 m cols)
#define VTP 72         // [64 t][VTP] V tile
__global__ __launch_bounds__(256) void scan_kernel(const float* __restrict__ V)
{
    extern __shared__ float sm[];
    float* kt = sm;              // [64 t][KTP2]
    float* vt = kt + 64*KTP2;    // [64 t][VTP]
    const int tid = threadIdx.x;
    const int w = tid >> 5, lane = tid & 31;
    const int lr = lane >> 2, lc = lane & 3;
    const int bh = blockIdx.x >> 4;
    const int ms = blockIdx.x & 15;
    const int m0 = ms*16;
    const int b = bh >> 3, h = bh & 7;
    const float alpha = RATIO * __expf(-g_kmax[bh]);

    float r0 = 0.f, r1 = 0.f, r2 = 0.f, r3 = 0.f;   // running prefix (16m x 8d warp tile)
    float zrun = 0.f;                                // tid<16: running z for m0+tid

    const int d0 = w*8 + lc*2;

    for (int c = 0; c < NCH; c++){
        const int lbase = c*CHK;
        __syncthreads();   // smem reusable

        // stage kp tile: 64t x 16m (1 float4 per thread)
        {
            int t = tid >> 2, m4 = (tid & 3)*4;
            float4 ev = *(const float4*)&g_E[((size_t)bh*Lc + lbase + t)*Mc + m0 + m4];
            float4 val;
            val.x = tf32f(fmaf(alpha, ev.x, BETA));
            val.y = tf32f(fmaf(alpha, ev.y, BETA));
            val.z = tf32f(fmaf(alpha, ev.z, BETA));
            val.w = tf32f(fmaf(alpha, ev.w, BETA));
            *(float4*)&kt[t*KTP2 + m4] = val;
        }
        // stage V tile: 64t x 64d
        {
            const size_t vbase = (((size_t)b*Lc + lbase)*Hc + h)*Dc;
            #pragma unroll
            for (int i = tid; i < 1024; i += 256){
                int t = i >> 4, d4 = (i & 15)*4;
                float4 v = *(const float4*)&V[vbase + (size_t)t*(Hc*Dc) + d4];
                *(float4*)&vt[t*VTP + d4] =
                    make_float4(tf32f(v.x), tf32f(v.y), tf32f(v.z), tf32f(v.w));
            }
        }

        // write EXCLUSIVE prefix for this chunk from running registers
        {
            const size_t Sb = ((size_t)bh*NCH + c)*Mc*Dc;
            *(float2*)&g_S[Sb + (size_t)(m0 + lr)*Dc + d0]     = make_float2(r0, r1);
            *(float2*)&g_S[Sb + (size_t)(m0 + 8 + lr)*Dc + d0] = make_float2(r2, r3);
            if (tid < 16) g_z[((size_t)bh*NCH + c)*Mc + m0 + tid] = zrun;
        }
        __syncthreads();

        // accumulate chunk: k-loop over t (8 steps)
        #pragma unroll
        for (int ks = 0; ks < 8; ks++){
            const int k0 = ks*8;
            uint32_t a0 = __float_as_uint(kt[(k0 + lc)*KTP2     + lr]);
            uint32_t a1 = __float_as_uint(kt[(k0 + lc)*KTP2     + 8 + lr]);
            uint32_t a2 = __float_as_uint(kt[(k0 + 4 + lc)*KTP2 + lr]);
            uint32_t a3 = __float_as_uint(kt[(k0 + 4 + lc)*KTP2 + 8 + lr]);
            uint32_t b0 = __float_as_uint(vt[(k0 + lc)*VTP     + w*8 + lr]);
            uint32_t b1 = __float_as_uint(vt[(k0 + 4 + lc)*VTP + w*8 + lr]);
            mma_tf32(r0, r1, r2, r3, a0, a1, a2, a3, b0, b1);
        }
        if (tid < 16){
            float zc = 0.f;
            #pragma unroll 8
            for (int t = 0; t < CHK; t++) zc += kt[t*KTP2 + tid];
            zrun += zc;
        }
    }
}

// ============================================================
// K5: mma.sync tf32 output kernel (unchanged from R11 winner).
// ============================================================
#define OP 68
__global__ __launch_bounds__(256,3) void out_kernel(const float* __restrict__ V,
                                                    float* __restrict__ Out)
{
    extern __shared__ float sm[];
    float* q_sm    = sm;            // [64 t][OP]  (aliased: A_sm after GEMM1)
    float* kp_sm   = sm + 64*OP;    // [64 s][OP]  (aliased: numI_sm)
    float* S_sm    = sm + 2*64*OP;  // [64 m][OP]  (aliased: v_sm)
    float* z_sm    = sm + 3*64*OP;          // [64]
    float* den_sm  = z_sm + 64;             // [64]
    float* denI_sm = den_sm + 64;           // [64]
    float* A_sm    = q_sm;
    float* numI_sm = kp_sm;
    float* v_sm    = S_sm;

    const int tid = threadIdx.x;
    const int w = tid >> 5, lane = tid & 31;
    const int tg = w & 3, ng = w >> 2;
    const int lr = lane >> 2, lc = lane & 3;
    const int bi = blockIdx.x;
    const int bh = bi >> 5, c = bi & 31;
    const int b = bh >> 3, h = bh & 7;
    const int lbase = c*CHK;
    const float alpha = RATIO * __expf(-g_kmax[bh]);

    const size_t qbase = ((size_t)bh*Lc + lbase)*Mc;
    const size_t Sb    = ((size_t)bh*NCH + c)*Mc*Dc;
    const size_t zbg   = ((size_t)bh*NCH + c)*Mc;
    const size_t vbase = (((size_t)b*Lc + lbase)*Hc + h)*Dc;

    const int t_lo = tg*16 + lr;
    const int t_hi = t_lo + 8;

    float acc[9][4];
    #pragma unroll
    for (int j = 0; j < 9; j++)
        #pragma unroll
        for (int r = 0; r < 4; r++) acc[j][r] = 0.f;

    // ================= GEMM1: loop over 4 m-tiles =================
    for (int m0 = 0; m0 < Mc; m0 += 64){
        __syncthreads();
        for (int i = tid; i < 1024; i += 256){
            int r = i >> 4, f4 = (i & 15)*4;
            float4 v = *(const float4*)&g_qp[qbase + (size_t)r*Mc + m0 + f4];
            *(float4*)&q_sm[r*OP + f4] =
                make_float4(tf32f(v.x), tf32f(v.y), tf32f(v.z), tf32f(v.w));
        }
        for (int i = tid; i < 1024; i += 256){
            int r = i >> 4, f4 = (i & 15)*4;
            float4 e = *(const float4*)&g_E[qbase + (size_t)r*Mc + m0 + f4];
            *(float4*)&kp_sm[r*OP + f4] =
                make_float4(tf32f(fmaf(alpha, e.x, BETA)), tf32f(fmaf(alpha, e.y, BETA)),
                            tf32f(fmaf(alpha, e.z, BETA)), tf32f(fmaf(alpha, e.w, BETA)));
        }
        for (int i = tid; i < 1024; i += 256){
            int r = i >> 4, f4 = (i & 15)*4;
            float4 v = *(const float4*)&g_S[Sb + (size_t)(m0 + r)*Dc + f4];
            *(float4*)&S_sm[r*OP + f4] =
                make_float4(tf32f(v.x), tf32f(v.y), tf32f(v.z), tf32f(v.w));
        }
        if (tid < 64) z_sm[tid] = tf32f(g_z[zbg + m0 + tid]);
        __syncthreads();

        #pragma unroll
        for (int ks = 0; ks < 8; ks++){
            const int k0 = ks*8;
            const float* ar = &q_sm[t_lo*OP + k0 + lc];
            uint32_t a0 = __float_as_uint(ar[0]);
            uint32_t a1 = __float_as_uint(ar[8*OP]);
            uint32_t a2 = __float_as_uint(ar[4]);
            uint32_t a3 = __float_as_uint(ar[8*OP + 4]);
            if (ng == 0){
                #pragma unroll
                for (int j = 0; j < 8; j++){
                    uint32_t b0 = __float_as_uint(kp_sm[(j*8 + lr)*OP + k0 + lc]);
                    uint32_t b1 = __float_as_uint(kp_sm[(j*8 + lr)*OP + k0 + 4 + lc]);
                    mma_tf32(acc[j][0], acc[j][1], acc[j][2], acc[j][3],
                             a0, a1, a2, a3, b0, b1);
                }
            } else {
                #pragma unroll
                for (int j = 0; j < 8; j++){
                    uint32_t b0 = __float_as_uint(S_sm[(k0 + lc)*OP + j*8 + lr]);
                    uint32_t b1 = __float_as_uint(S_sm[(k0 + 4 + lc)*OP + j*8 + lr]);
                    mma_tf32(acc[j][0], acc[j][1], acc[j][2], acc[j][3],
                             a0, a1, a2, a3, b0, b1);
                }
                uint32_t b0 = (lr == 0) ? __float_as_uint(z_sm[k0 + lc]) : 0u;
                uint32_t b1 = (lr == 0) ? __float_as_uint(z_sm[k0 + 4 + lc]) : 0u;
                mma_tf32(acc[8][0], acc[8][1], acc[8][2], acc[8][3],
                         a0, a1, a2, a3, b0, b1);
            }
        }
    }
    __syncthreads();

    // ================= epilogue =================
    if (ng == 0){
        float sum_lo = 0.f, sum_hi = 0.f;
        #pragma unroll
        for (int j = 0; j < 8; j++){
            int s0 = j*8 + lc*2;
            float v0 = (s0     <= t_lo) ? acc[j][0] : 0.f;
            float v1 = (s0 + 1 <= t_lo) ? acc[j][1] : 0.f;
            float v2 = (s0     <= t_hi) ? acc[j][2] : 0.f;
            float v3 = (s0 + 1 <= t_hi) ? acc[j][3] : 0.f;
            sum_lo += v0 + v1;
            sum_hi += v2 + v3;
            A_sm[t_lo*OP + s0]     = tf32f(v0);
            A_sm[t_lo*OP + s0 + 1] = tf32f(v1);
            A_sm[t_hi*OP + s0]     = tf32f(v2);
            A_sm[t_hi*OP + s0 + 1] = tf32f(v3);
        }
        sum_lo += __shfl_xor_sync(0xffffffffu, sum_lo, 1);
        sum_lo += __shfl_xor_sync(0xffffffffu, sum_lo, 2);
        sum_hi += __shfl_xor_sync(0xffffffffu, sum_hi, 1);
        sum_hi += __shfl_xor_sync(0xffffffffu, sum_hi, 2);
        if (lc == 0){ den_sm[t_lo] = sum_lo; den_sm[t_hi] = sum_hi; }
    } else {
        #pragma unroll
        for (int j = 0; j < 8; j++){
            int d0 = j*8 + lc*2;
            numI_sm[t_lo*OP + d0]     = acc[j][0];
            numI_sm[t_lo*OP + d0 + 1] = acc[j][1];
            numI_sm[t_hi*OP + d0]     = acc[j][2];
            numI_sm[t_hi*OP + d0 + 1] = acc[j][3];
        }
        if (lc == 0){ denI_sm[t_lo] = acc[8][0]; denI_sm[t_hi] = acc[8][2]; }
    }
    for (int i = tid; i < 1024; i += 256){
        int s = i >> 4, f4 = (i & 15)*4;
        float4 v = *(const float4*)&V[vbase + (size_t)s*(Hc*Dc) + f4];
        *(float4*)&v_sm[s*OP + f4] =
            make_float4(tf32f(v.x), tf32f(v.y), tf32f(v.z), tf32f(v.w));
    }
    __syncthreads();

    // ================= GEMM2: num = numI + A V =================
    const int d0base = ng*32;
    float cc[4][4];
    #pragma unroll
    for (int j = 0; j < 4; j++){
        int d0 = d0base + j*8 + lc*2;
        cc[j][0] = numI_sm[t_lo*OP + d0];
        cc[j][1] = numI_sm[t_lo*OP + d0 + 1];
        cc[j][2] = numI_sm[t_hi*OP + d0];
        cc[j][3] = numI_sm[t_hi*OP + d0 + 1];
    }
    #pragma unroll
    for (int ks = 0; ks < 8; ks++){
        const int s0 = ks*8;
        const float* ar = &A_sm[t_lo*OP + s0 + lc];
        uint32_t a0 = __float_as_uint(ar[0]);
        uint32_t a1 = __float_as_uint(ar[8*OP]);
        uint32_t a2 = __float_as_uint(ar[4]);
        uint32_t a3 = __float_as_uint(ar[8*OP + 4]);
        #pragma unroll
        for (int j = 0; j < 4; j++){
            int d0 = d0base + j*8;
            uint32_t b0 = __float_as_uint(v_sm[(s0 + lc)*OP + d0 + lr]);
            uint32_t b1 = __float_as_uint(v_sm[(s0 + 4 + lc)*OP + d0 + lr]);
            mma_tf32(cc[j][0], cc[j][1], cc[j][2], cc[j][3],
                     a0, a1, a2, a3, b0, b1);
        }
    }

    // ================= normalize + store =================
    float denL = den_sm[t_lo] + denI_sm[t_lo];
    float denH = den_sm[t_hi] + denI_sm[t_hi];
    if (fabsf(denL) <= 1e-6f) denL += 2e-6f;
    if (fabsf(denH) <= 1e-6f) denH += 2e-6f;
    float invL = 1.0f / denL;
    float invH = 1.0f / denH;

    float* orowL = Out + (((size_t)b*Lc + lbase + t_lo)*Hc + h)*Dc;
    float* orowH = Out + (((size_t)b*Lc + lbase + t_hi)*Hc + h)*Dc;
    #pragma unroll
    for (int j = 0; j < 4; j++){
        int d0 = d0base + j*8 + lc*2;
        *(float2*)&orowL[d0] = make_float2(cc[j][0]*invL, cc[j][1]*invL);
        *(float2*)&orowH[d0] = make_float2(cc[j][2]*invH, cc[j][3]*invH);
    }
}

// ============================================================
extern "C" void kernel_launch(void* const* d_in, const int* in_sizes, int n_in,
                              void* d_out, int out_size)
{
    const float* Q = (const float*)d_in[0];
    const float* K = (const float*)d_in[1];
    const float* V = (const float*)d_in[2];
    const float* P = (const float*)d_in[3];
    float* O = (float*)d_out;

    const int SM1 = (4*64*OPF + 64 + 128) * 4;      // ~70.4 KB
    const int SMS = (64*KTP2 + 64*VTP) * 4;         // ~24.6 KB
    const int SM5 = (3*64*OP + 64*3) * 4;           // ~53 KB

    cudaFuncSetAttribute(feat_kernel, cudaFuncAttributeMaxDynamicSharedMemorySize, SM1);
    cudaFuncSetAttribute(scan_kernel, cudaFuncAttributeMaxDynamicSharedMemorySize, SMS);
    cudaFuncSetAttribute(out_kernel,  cudaFuncAttributeMaxDynamicSharedMemorySize, SM5);

    init_kernel<<<1, 32>>>();
    feat_kernel<<<NROWS/64, 256, SM1>>>(Q, P, 1);
    feat_kernel<<<NROWS/64, 256, SM1>>>(K, P, 0);
    scan_kernel<<<BH*16, 256, SMS>>>(V);
    out_kernel<<<BH*NCH, 256, SM5>>>(V, O);
}

// round 17
// speedup vs baseline: 1.1428x; 1.1428x over previous
#include <cuda_runtime.h>
#include <math.h>
#include <stdint.h>

// Problem dims (fixed)
#define Bc 4
#define Lc 2048
#define Hc 8
#define Dc 64
#define Mc 256
#define CHK 64
#define NCH (Lc/CHK)         // 32
#define BH (Bc*Hc)           // 32
#define NROWS (Bc*Lc*Hc)     // 65536

#define NORMC 0.35355339059327373f   // 64^(-1/4)
#define RATIO 0.0625f                // 1/sqrt(256)
#define DIAGC 0.0625f                // 0.5 * 64^(-1/2)
#define KEPS  1e-4f
#define BETA  (RATIO*KEPS)

// ----- scratch (static device arrays; no allocation) -----
__device__ float g_qp [(size_t)BH*Lc*Mc];      // 64 MB [bh][l][m] query features
__device__ float g_E  [(size_t)BH*Lc*Mc];      // 64 MB exp(dash - diag) for keys
__device__ float g_S  [(size_t)BH*NCH*Mc*Dc];  // 64 MB chunk states [m][d] -> excl prefix
__device__ float g_z  [(size_t)BH*NCH*Mc];
__device__ float g_kmax[BH];                   // memset 0xFE -> ~-1.69e38 sentinel

__device__ __forceinline__ void atomicMaxF(float* addr, float v){
    int old = __float_as_int(*addr);
    while (__int_as_float(old) < v){
        int assumed = old;
        old = atomicCAS((int*)addr, assumed, __float_as_int(v));
        if (old == assumed) break;
    }
}

// fp32 -> tf32 (round-to-nearest), kept in a float register slot
__device__ __forceinline__ float tf32f(float f){
    uint32_t r;
    asm("cvt.rna.tf32.f32 %0, %1;" : "=r"(r) : "f"(f));
    return __uint_as_float(r);
}

__device__ __forceinline__ void mma_tf32(float& d0, float& d1, float& d2, float& d3,
                                         uint32_t a0, uint32_t a1, uint32_t a2, uint32_t a3,
                                         uint32_t b0, uint32_t b1){
    asm volatile("mma.sync.aligned.m16n8k8.row.col.f32.tf32.tf32.f32 "
        "{%0,%1,%2,%3}, {%4,%5,%6,%7}, {%8,%9}, {%0,%1,%2,%3};"
        : "+f"(d0), "+f"(d1), "+f"(d2), "+f"(d3)
        : "r"(a0), "r"(a1), "r"(a2), "r"(a3), "r"(b0), "r"(b1));
}

// ============================================================
// K1: features via mma.sync tf32x3, 64 rows/block.
// MERGED: grid 2048 — blocks [0,1024) do Q, [1024,2048) do K.
// ============================================================
#define OPF 68

__global__ __launch_bounds__(256,2) void feat_kernel(const float* __restrict__ Q,
                                                     const float* __restrict__ K,
                                                     const float* __restrict__ P)
{
    extern __shared__ float sm[];
    float* X1   = sm;                 // [64][OPF]
    float* X2   = X1 + 64*OPF;        // [64][OPF]
    float* P1   = X2 + 64*OPF;        // [64][OPF]
    float* P2   = P1 + 64*OPF;        // [64][OPF]
    float* ssd  = P2 + 64*OPF;        // [64]
    float* pmax = ssd + 64;           // [2][64]

    const int tid = threadIdx.x;
    const int w = tid >> 5, lane = tid & 31;
    const int lr = lane >> 2, lc = lane & 3;
    const int tg = w & 3, nh = w >> 2;
    const int isQuery = (blockIdx.x < 1024) ? 1 : 0;
    const int row0 = (blockIdx.x & 1023) * 64;
    const float* X = isQuery ? Q : K;

    // stage X~ = NORMC*X split into tf32 hi/lo
    for (int i = tid; i < 1024; i += 256){
        int r = i >> 4, d4 = (i & 15)*4;
        float4 v = *(const float4*)&X[(size_t)(row0 + r)*Dc + d4];
        float4 xt = make_float4(v.x*NORMC, v.y*NORMC, v.z*NORMC, v.w*NORMC);
        float4 h = make_float4(tf32f(xt.x), tf32f(xt.y), tf32f(xt.z), tf32f(xt.w));
        float4 l = make_float4(tf32f(xt.x - h.x), tf32f(xt.y - h.y),
                               tf32f(xt.z - h.z), tf32f(xt.w - h.w));
        *(float4*)&X1[r*OPF + d4] = h;
        *(float4*)&X2[r*OPF + d4] = l;
    }
    __syncthreads();

    if (tid < 64){
        float s = 0.f;
        #pragma unroll
        for (int d = 0; d < 64; d++){
            float v = X1[tid*OPF + d] + X2[tid*OPF + d];
            s += v*v;
        }
        ssd[tid] = 0.5f * s;          // == DIAGC * sum(x^2)
    }

    const int t_lo = tg*16 + lr;
    const int t_hi = t_lo + 8;

    float acc[16][4];
    #pragma unroll
    for (int j = 0; j < 16; j++)
        #pragma unroll
        for (int r = 0; r < 4; r++) acc[j][r] = 0.f;

    // ---- m loop: 4 tiles of 64 ----
    for (int mt = 0; mt < 4; mt++){
        __syncthreads();
        for (int i = tid; i < 1024; i += 256){
            int mm = i >> 4, d4 = (i & 15)*4;
            float4 v = *(const float4*)&P[(size_t)(mt*64 + mm)*Dc + d4];
            float4 h = make_float4(tf32f(v.x), tf32f(v.y), tf32f(v.z), tf32f(v.w));
            float4 l = make_float4(tf32f(v.x - h.x), tf32f(v.y - h.y),
                                   tf32f(v.z - h.z), tf32f(v.w - h.w));
            *(float4*)&P1[mm*OPF + d4] = h;
            *(float4*)&P2[mm*OPF + d4] = l;
        }
        __syncthreads();

        #pragma unroll
        for (int ks = 0; ks < 8; ks++){
            const int k0 = ks*8;
            const float* a1p = &X1[t_lo*OPF + k0 + lc];
            const float* a2p = &X2[t_lo*OPF + k0 + lc];
            uint32_t a10 = __float_as_uint(a1p[0]);
            uint32_t a11 = __float_as_uint(a1p[8*OPF]);
            uint32_t a12 = __float_as_uint(a1p[4]);
            uint32_t a13 = __float_as_uint(a1p[8*OPF + 4]);
            uint32_t a20 = __float_as_uint(a2p[0]);
            uint32_t a21 = __float_as_uint(a2p[8*OPF]);
            uint32_t a22 = __float_as_uint(a2p[4]);
            uint32_t a23 = __float_as_uint(a2p[8*OPF + 4]);
            #pragma unroll
            for (int j = 0; j < 4; j++){
                const int nrow = nh*32 + j*8 + lr;
                uint32_t b10 = __float_as_uint(P1[nrow*OPF + k0 + lc]);
                uint32_t b11 = __float_as_uint(P1[nrow*OPF + k0 + 4 + lc]);
                uint32_t b20 = __float_as_uint(P2[nrow*OPF + k0 + lc]);
                uint32_t b21 = __float_as_uint(P2[nrow*OPF + k0 + 4 + lc]);
                const int jj = mt*4 + j;
                mma_tf32(acc[jj][0], acc[jj][1], acc[jj][2], acc[jj][3],
                         a10, a11, a12, a13, b10, b11);
                mma_tf32(acc[jj][0], acc[jj][1], acc[jj][2], acc[jj][3],
                         a20, a21, a22, a23, b10, b11);
                mma_tf32(acc[jj][0], acc[jj][1], acc[jj][2], acc[jj][3],
                         a10, a11, a12, a13, b20, b21);
            }
        }
    }

    // ---- row max ----
    float mxL = -3.0e38f, mxH = -3.0e38f;
    #pragma unroll
    for (int jj = 0; jj < 16; jj++){
        mxL = fmaxf(mxL, fmaxf(acc[jj][0], acc[jj][1]));
        mxH = fmaxf(mxH, fmaxf(acc[jj][2], acc[jj][3]));
    }
    mxL = fmaxf(mxL, __shfl_xor_sync(0xffffffffu, mxL, 1));
    mxL = fmaxf(mxL, __shfl_xor_sync(0xffffffffu, mxL, 2));
    mxH = fmaxf(mxH, __shfl_xor_sync(0xffffffffu, mxH, 1));
    mxH = fmaxf(mxH, __shfl_xor_sync(0xffffffffu, mxH, 2));
    __syncthreads();
    if (lc == 0){
        pmax[nh*64 + t_lo] = mxL;
        pmax[nh*64 + t_hi] = mxH;
    }
    __syncthreads();
    mxL = fmaxf(pmax[t_lo], pmax[64 + t_lo]);
    mxH = fmaxf(pmax[t_hi], pmax[64 + t_hi]);

    const int growL = row0 + t_lo;
    const int growH = row0 + t_hi;
    const int bhL = ((growL >> 3) >> 11)*Hc + (growL & 7);
    const int lL  = (growL >> 3) & 2047;
    const int bhH = ((growH >> 3) >> 11)*Hc + (growH & 7);
    const int lH  = (growH >> 3) & 2047;
    const float diagL = ssd[t_lo];
    const float diagH = ssd[t_hi];
    const size_t drowL = ((size_t)bhL*Lc + lL)*Mc;
    const size_t drowH = ((size_t)bhH*Lc + lH)*Mc;

    if (isQuery){
        #pragma unroll
        for (int jj = 0; jj < 16; jj++){
            const int col = (jj >> 2)*64 + nh*32 + (jj & 3)*8 + lc*2;
            float2 oL = make_float2(
                RATIO * (__expf(acc[jj][0] - diagL - mxL) + KEPS),
                RATIO * (__expf(acc[jj][1] - diagL - mxL) + KEPS));
            float2 oH = make_float2(
                RATIO * (__expf(acc[jj][2] - diagH - mxH) + KEPS),
                RATIO * (__expf(acc[jj][3] - diagH - mxH) + KEPS));
            *(float2*)&g_qp[drowL + col] = oL;
            *(float2*)&g_qp[drowH + col] = oH;
        }
    } else {
        #pragma unroll
        for (int jj = 0; jj < 16; jj++){
            const int col = (jj >> 2)*64 + nh*32 + (jj & 3)*8 + lc*2;
            float2 oL = make_float2(__expf(acc[jj][0] - diagL),
                                    __expf(acc[jj][1] - diagL));
            float2 oH = make_float2(__expf(acc[jj][2] - diagH),
                                    __expf(acc[jj][3] - diagH));
            *(float2*)&g_E[drowL + col] = oL;
            *(float2*)&g_E[drowH + col] = oH;
        }
        if (nh == 0 && lc == 0){
            atomicMaxF(&g_kmax[bhL], mxL);
            atomicMaxF(&g_kmax[bhH], mxH);
        }
    }
}

// ============================================================
// K3: state via mma.sync tf32 (R11 winner, unchanged).
// ============================================================
#define KTP 136
#define VTP 72
__global__ __launch_bounds__(256,3) void state_kernel(const float* __restrict__ V)
{
    extern __shared__ float sm[];
    float* kt = sm;              // [64 t][KTP]
    float* vt = kt + 64*KTP;     // [64 t][VTP]
    const int tid = threadIdx.x;
    const int w = tid >> 5, lane = tid & 31;
    const int lr = lane >> 2, lc = lane & 3;
    const int bi = blockIdx.x;
    const int bh = bi >> 6;
    const int rest = bi & 63;
    const int c = rest >> 1, half = rest & 1;
    const int b = bh >> 3, h = bh & 7;
    const float alpha = RATIO * __expf(-g_kmax[bh]);
    const int lbase = c*CHK;
    const int mh0 = half*128;
    const size_t base_lm = ((size_t)bh*Lc + lbase)*Mc + mh0;
    const size_t vbase = (((size_t)b*Lc + lbase)*Hc + h)*Dc;

    for (int i = tid; i < 2048; i += 256){
        int t = i >> 5, m4 = (i & 31) * 4;
        float4 ev = *(const float4*)&g_E[base_lm + (size_t)t*Mc + m4];
        *(float4*)&kt[t*KTP + m4] =
            make_float4(tf32f(fmaf(alpha, ev.x, BETA)), tf32f(fmaf(alpha, ev.y, BETA)),
                        tf32f(fmaf(alpha, ev.z, BETA)), tf32f(fmaf(alpha, ev.w, BETA)));
    }
    for (int i = tid; i < 1024; i += 256){
        int t = i >> 4, d4 = (i & 15) * 4;
        float4 v = *(const float4*)&V[vbase + (size_t)t*(Hc*Dc) + d4];
        *(float4*)&vt[t*VTP + d4] =
            make_float4(tf32f(v.x), tf32f(v.y), tf32f(v.z), tf32f(v.w));
    }
    __syncthreads();

    const int wm = w*16;
    float acc[8][4];
    #pragma unroll
    for (int j = 0; j < 8; j++)
        #pragma unroll
        for (int r = 0; r < 4; r++) acc[j][r] = 0.f;

    #pragma unroll
    for (int ks = 0; ks < 8; ks++){
        const int k0 = ks*8;
        uint32_t a0 = __float_as_uint(kt[(k0 + lc)*KTP     + wm + lr]);
        uint32_t a1 = __float_as_uint(kt[(k0 + lc)*KTP     + wm + 8 + lr]);
        uint32_t a2 = __float_as_uint(kt[(k0 + 4 + lc)*KTP + wm + lr]);
        uint32_t a3 = __float_as_uint(kt[(k0 + 4 + lc)*KTP + wm + 8 + lr]);
        #pragma unroll
        for (int j = 0; j < 8; j++){
            uint32_t b0 = __float_as_uint(vt[(k0 + lc)*VTP     + j*8 + lr]);
            uint32_t b1 = __float_as_uint(vt[(k0 + 4 + lc)*VTP + j*8 + lr]);
            mma_tf32(acc[j][0], acc[j][1], acc[j][2], acc[j][3],
                     a0, a1, a2, a3, b0, b1);
        }
    }

    const size_t Sbase = ((size_t)bh*NCH + c)*Mc*Dc + (size_t)mh0*Dc;
    #pragma unroll
    for (int j = 0; j < 8; j++){
        int d0 = j*8 + lc*2;
        *(float2*)&g_S[Sbase + (size_t)(wm + lr)*Dc + d0]     = make_float2(acc[j][0], acc[j][1]);
        *(float2*)&g_S[Sbase + (size_t)(wm + 8 + lr)*Dc + d0] = make_float2(acc[j][2], acc[j][3]);
    }

    if (tid < 128){
        float zv = 0.f;
        #pragma unroll 8
        for (int t = 0; t < CHK; t++) zv += kt[t*KTP + tid];
        g_z[((size_t)bh*NCH + c)*Mc + mh0 + tid] = zv;
    }
}

// ============================================================
// K4: exclusive prefix over 32 chunks — float4 chains (R13).
// ============================================================
__global__ __launch_bounds__(256) void prefix_kernel()
{
    const int bh = blockIdx.x >> 4;
    const int sl = blockIdx.x & 15;
    const int tid = threadIdx.x;
    const int e4 = ((sl << 8) + tid) * 4;

    size_t idx = (size_t)bh*NCH*Mc*Dc + e4;
    float4 run = make_float4(0.f, 0.f, 0.f, 0.f);
    #pragma unroll
    for (int c2 = 0; c2 < NCH; c2++){
        float4 tmp = *(float4*)&g_S[idx];
        *(float4*)&g_S[idx] = run;
        run.x += tmp.x; run.y += tmp.y; run.z += tmp.z; run.w += tmp.w;
        idx += (size_t)Mc*Dc;
    }
    if (sl == 0){
        size_t zi = (size_t)bh*NCH*Mc + tid;
        float zr = 0.f;
        #pragma unroll
        for (int c2 = 0; c2 < NCH; c2++){
            float tmp = g_z[zi]; g_z[zi] = zr; zr += tmp; zi += Mc;
        }
    }
}

// ============================================================
// K5: mma.sync tf32 output kernel (R11 winner, unchanged).
// ============================================================
#define OP 68
__global__ __launch_bounds__(256,3) void out_kernel(const float* __restrict__ V,
                                                    float* __restrict__ Out)
{
    extern __shared__ float sm[];
    float* q_sm    = sm;            // [64 t][OP]  (aliased: A_sm after GEMM1)
    float* kp_sm   = sm + 64*OP;    // [64 s][OP]  (aliased: numI_sm)
    float* S_sm    = sm + 2*64*OP;  // [64 m][OP]  (aliased: v_sm)
    float* z_sm    = sm + 3*64*OP;          // [64]
    float* den_sm  = z_sm + 64;             // [64]
    float* denI_sm = den_sm + 64;           // [64]
    float* A_sm    = q_sm;
    float* numI_sm = kp_sm;
    float* v_sm    = S_sm;

    const int tid = threadIdx.x;
    const int w = tid >> 5, lane = tid & 31;
    const int tg = w & 3, ng = w >> 2;
    const int lr = lane >> 2, lc = lane & 3;
    const int bi = blockIdx.x;
    const int bh = bi >> 5, c = bi & 31;
    const int b = bh >> 3, h = bh & 7;
    const int lbase = c*CHK;
    const float alpha = RATIO * __expf(-g_kmax[bh]);

    const size_t qbase = ((size_t)bh*Lc + lbase)*Mc;
    const size_t Sb    = ((size_t)bh*NCH + c)*Mc*Dc;
    const size_t zbg   = ((size_t)bh*NCH + c)*Mc;
    const size_t vbase = (((size_t)b*Lc + lbase)*Hc + h)*Dc;

    const int t_lo = tg*16 + lr;
    const int t_hi = t_lo + 8;

    float acc[9][4];
    #pragma unroll
    for (int j = 0; j < 9; j++)
        #pragma unroll
        for (int r = 0; r < 4; r++) acc[j][r] = 0.f;

    // ================= GEMM1: loop over 4 m-tiles =================
    for (int m0 = 0; m0 < Mc; m0 += 64){
        __syncthreads();
        for (int i = tid; i < 1024; i += 256){
            int r = i >> 4, f4 = (i & 15)*4;
            float4 v = *(const float4*)&g_qp[qbase + (size_t)r*Mc + m0 + f4];
            *(float4*)&q_sm[r*OP + f4] =
                make_float4(tf32f(v.x), tf32f(v.y), tf32f(v.z), tf32f(v.w));
        }
        for (int i = tid; i < 1024; i += 256){
            int r = i >> 4, f4 = (i & 15)*4;
            float4 e = *(const float4*)&g_E[qbase + (size_t)r*Mc + m0 + f4];
            *(float4*)&kp_sm[r*OP + f4] =
                make_float4(tf32f(fmaf(alpha, e.x, BETA)), tf32f(fmaf(alpha, e.y, BETA)),
                            tf32f(fmaf(alpha, e.z, BETA)), tf32f(fmaf(alpha, e.w, BETA)));
        }
        for (int i = tid; i < 1024; i += 256){
            int r = i >> 4, f4 = (i & 15)*4;
            float4 v = *(const float4*)&g_S[Sb + (size_t)(m0 + r)*Dc + f4];
            *(float4*)&S_sm[r*OP + f4] =
                make_float4(tf32f(v.x), tf32f(v.y), tf32f(v.z), tf32f(v.w));
        }
        if (tid < 64) z_sm[tid] = tf32f(g_z[zbg + m0 + tid]);
        __syncthreads();

        #pragma unroll
        for (int ks = 0; ks < 8; ks++){
            const int k0 = ks*8;
            const float* ar = &q_sm[t_lo*OP + k0 + lc];
            uint32_t a0 = __float_as_uint(ar[0]);
            uint32_t a1 = __float_as_uint(ar[8*OP]);
            uint32_t a2 = __float_as_uint(ar[4]);
            uint32_t a3 = __float_as_uint(ar[8*OP + 4]);
            if (ng == 0){
                #pragma unroll
                for (int j = 0; j < 8; j++){
                    uint32_t b0 = __float_as_uint(kp_sm[(j*8 + lr)*OP + k0 + lc]);
                    uint32_t b1 = __float_as_uint(kp_sm[(j*8 + lr)*OP + k0 + 4 + lc]);
                    mma_tf32(acc[j][0], acc[j][1], acc[j][2], acc[j][3],
                             a0, a1, a2, a3, b0, b1);
                }
            } else {
                #pragma unroll
                for (int j = 0; j < 8; j++){
                    uint32_t b0 = __float_as_uint(S_sm[(k0 + lc)*OP + j*8 + lr]);
                    uint32_t b1 = __float_as_uint(S_sm[(k0 + 4 + lc)*OP + j*8 + lr]);
                    mma_tf32(acc[j][0], acc[j][1], acc[j][2], acc[j][3],
                             a0, a1, a2, a3, b0, b1);
                }
                uint32_t b0 = (lr == 0) ? __float_as_uint(z_sm[k0 + lc]) : 0u;
                uint32_t b1 = (lr == 0) ? __float_as_uint(z_sm[k0 + 4 + lc]) : 0u;
                mma_tf32(acc[8][0], acc[8][1], acc[8][2], acc[8][3],
                         a0, a1, a2, a3, b0, b1);
            }
        }
    }
    __syncthreads();

    // ================= epilogue =================
    if (ng == 0){
        float sum_lo = 0.f, sum_hi = 0.f;
        #pragma unroll
        for (int j = 0; j < 8; j++){
            int s0 = j*8 + lc*2;
            float v0 = (s0     <= t_lo) ? acc[j][0] : 0.f;
            float v1 = (s0 + 1 <= t_lo) ? acc[j][1] : 0.f;
            float v2 = (s0     <= t_hi) ? acc[j][2] : 0.f;
            float v3 = (s0 + 1 <= t_hi) ? acc[j][3] : 0.f;
            sum_lo += v0 + v1;
            sum_hi += v2 + v3;
            A_sm[t_lo*OP + s0]     = tf32f(v0);
            A_sm[t_lo*OP + s0 + 1] = tf32f(v1);
            A_sm[t_hi*OP + s0]     = tf32f(v2);
            A_sm[t_hi*OP + s0 + 1] = tf32f(v3);
        }
        sum_lo += __shfl_xor_sync(0xffffffffu, sum_lo, 1);
        sum_lo += __shfl_xor_sync(0xffffffffu, sum_lo, 2);
        sum_hi += __shfl_xor_sync(0xffffffffu, sum_hi, 1);
        sum_hi += __shfl_xor_sync(0xffffffffu, sum_hi, 2);
        if (lc == 0){ den_sm[t_lo] = sum_lo; den_sm[t_hi] = sum_hi; }
    } else {
        #pragma unroll
        for (int j = 0; j < 8; j++){
            int d0 = j*8 + lc*2;
            numI_sm[t_lo*OP + d0]     = acc[j][0];
            numI_sm[t_lo*OP + d0 + 1] = acc[j][1];
            numI_sm[t_hi*OP + d0]     = acc[j][2];
            numI_sm[t_hi*OP + d0 + 1] = acc[j][3];
        }
        if (lc == 0){ denI_sm[t_lo] = acc[8][0]; denI_sm[t_hi] = acc[8][2]; }
    }
    for (int i = tid; i < 1024; i += 256){
        int s = i >> 4, f4 = (i & 15)*4;
        float4 v = *(const float4*)&V[vbase + (size_t)s*(Hc*Dc) + f4];
        *(float4*)&v_sm[s*OP + f4] =
            make_float4(tf32f(v.x), tf32f(v.y), tf32f(v.z), tf32f(v.w));
    }
    __syncthreads();

    // ================= GEMM2: num = numI + A V =================
    const int d0base = ng*32;
    float cc[4][4];
    #pragma unroll
    for (int j = 0; j < 4; j++){
        int d0 = d0base + j*8 + lc*2;
        cc[j][0] = numI_sm[t_lo*OP + d0];
        cc[j][1] = numI_sm[t_lo*OP + d0 + 1];
        cc[j][2] = numI_sm[t_hi*OP + d0];
        cc[j][3] = numI_sm[t_hi*OP + d0 + 1];
    }
    #pragma unroll
    for (int ks = 0; ks < 8; ks++){
        const int s0 = ks*8;
        const float* ar = &A_sm[t_lo*OP + s0 + lc];
        uint32_t a0 = __float_as_uint(ar[0]);
        uint32_t a1 = __float_as_uint(ar[8*OP]);
        uint32_t a2 = __float_as_uint(ar[4]);
        uint32_t a3 = __float_as_uint(ar[8*OP + 4]);
        #pragma unroll
        for (int j = 0; j < 4; j++){
            int d0 = d0base + j*8;
            uint32_t b0 = __float_as_uint(v_sm[(s0 + lc)*OP + d0 + lr]);
            uint32_t b1 = __float_as_uint(v_sm[(s0 + 4 + lc)*OP + d0 + lr]);
            mma_tf32(cc[j][0], cc[j][1], cc[j][2], cc[j][3],
                     a0, a1, a2, a3, b0, b1);
        }
    }

    // ================= normalize + store =================
    float denL = den_sm[t_lo] + denI_sm[t_lo];
    float denH = den_sm[t_hi] + denI_sm[t_hi];
    if (fabsf(denL) <= 1e-6f) denL += 2e-6f;
    if (fabsf(denH) <= 1e-6f) denH += 2e-6f;
    float invL = 1.0f / denL;
    float invH = 1.0f / denH;

    float* orowL = Out + (((size_t)b*Lc + lbase + t_lo)*Hc + h)*Dc;
    float* orowH = Out + (((size_t)b*Lc + lbase + t_hi)*Hc + h)*Dc;
    #pragma unroll
    for (int j = 0; j < 4; j++){
        int d0 = d0base + j*8 + lc*2;
        *(float2*)&orowL[d0] = make_float2(cc[j][0]*invL, cc[j][1]*invL);
        *(float2*)&orowH[d0] = make_float2(cc[j][2]*invH, cc[j][3]*invH);
    }
}

// ============================================================
extern "C" void kernel_launch(void* const* d_in, const int* in_sizes, int n_in,
                              void* d_out, int out_size)
{
    const float* Q = (const float*)d_in[0];
    const float* K = (const float*)d_in[1];
    const float* V = (const float*)d_in[2];
    const float* P = (const float*)d_in[3];
    float* O = (float*)d_out;

    const int SM1 = (4*64*OPF + 64 + 128) * 4;      // ~70.4 KB
    const int SM3 = (64*KTP + 64*VTP) * 4;          // ~52 KB
    const int SM5 = (3*64*OP + 64*3) * 4;           // ~53 KB

    cudaFuncSetAttribute(feat_kernel,  cudaFuncAttributeMaxDynamicSharedMemorySize, SM1);
    cudaFuncSetAttribute(state_kernel, cudaFuncAttributeMaxDynamicSharedMemorySize, SM3);
    cudaFuncSetAttribute(out_kernel,   cudaFuncAttributeMaxDynamicSharedMemorySize, SM5);

    // init g_kmax to ~-1.69e38 via byte pattern 0xFE (graph-capturable memset)
    void* kmax_ptr = nullptr;
    cudaGetSymbolAddress(&kmax_ptr, g_kmax);
    cudaMemsetAsync(kmax_ptr, 0xFE, BH * sizeof(float));

    feat_kernel<<<2048, 256, SM1>>>(Q, K, P);       // merged Q+K features
    state_kernel<<<BH*NCH*2, 256, SM3>>>(V);
    prefix_kernel<<<BH*16, 256>>>();
    out_kernel<<<BH*NCH, 256, SM5>>>(V, O);
}